// round 13
// baseline (speedup 1.0000x reference)
#include <cuda_runtime.h>
#include <cuda_fp16.h>

#define BLOCK 256
#define TSEQ  200
#define NELEM 32768
#define NGROUPS (NELEM / 8)     // 8 elements per warp-sequence

typedef unsigned long long u64;

__device__ unsigned int g_ctr;

__global__ void init_ctr_kernel() { g_ctr = 0u; }

// ---- tanh.approx-based activations (MUFU.TANH: ~1.4e-5 abs err) ----
__device__ __forceinline__ float tanha_(float x) {
    float y; asm("tanh.approx.f32 %0, %1;" : "=f"(y) : "f"(x)); return y;
}

// ---- packed f32x2 ops ----
__device__ __forceinline__ u64 fma2(u64 a, u64 b, u64 c) {
    u64 d; asm("fma.rn.f32x2 %0, %1, %2, %3;" : "=l"(d) : "l"(a), "l"(b), "l"(c));
    return d;
}
__device__ __forceinline__ u64 pack2(float lo, float hi) {
    u64 r; asm("mov.b64 %0, {%1, %2};" : "=l"(r) : "f"(lo), "f"(hi)); return r;
}
__device__ __forceinline__ void unpack2(float& lo, float& hi, u64 v) {
    asm("mov.b64 {%0, %1}, %2;" : "=f"(lo), "=f"(hi) : "l"(v));
}
__device__ __forceinline__ void prefetchL2_(const void* p) {
    asm volatile("prefetch.global.L2 [%0];" :: "l"(p));
}

// smem layout:
//   [0 .. 51200)  : fp16 Wout packs, [800 phys-col][4 r][4 qpack] uint32
//                   phys col (4t+s) for r-class r = logical col 4t+(s^r)
//   [51200 .. +512): layer-2 gate weights, u64 wg1[4 r][2 which][8 in]
#define SMW16   12800
#define WG1_U64 6400            // u64 index of wg1 area
#define SM_BYTES (51200 + 512)

// one LSTM unit step. gIF lanes=(i,f), gGO lanes=(g,o).
// i/f/o rows and biases PRE-SCALED by 0.5 -> sigmoid = fma(tanh,.5,.5).
// Works for register-resident or smem-resident weight arrays.
__device__ __forceinline__ float unit_step(
    const u64* __restrict__ inA, const u64* __restrict__ inB,
    const u64* __restrict__ wIF, const u64* __restrict__ wGO,
    u64 bIF, u64 bGO, float& c)
{
    u64 gIF = bIF, gGO = bGO;
    #pragma unroll
    for (int in = 0; in < 4; in++) {
        gIF = fma2(inA[in], wIF[in], gIF);
        gGO = fma2(inA[in], wGO[in], gGO);
    }
    #pragma unroll
    for (int in = 0; in < 4; in++) {
        gIF = fma2(inB[in], wIF[4 + in], gIF);
        gGO = fma2(inB[in], wGO[4 + in], gGO);
    }
    float iv, fv, gv, ov;
    unpack2(iv, fv, gIF);
    unpack2(gv, ov, gGO);
    float ti = tanha_(iv), tf = tanha_(fv), tg = tanha_(gv), to = tanha_(ov);
    float si = fmaf(ti, 0.5f, 0.5f);
    float sf = fmaf(tf, 0.5f, 0.5f);
    float so = fmaf(to, 0.5f, 0.5f);
    c = fmaf(sf, c, si * tg);
    return so * tanha_(c);
}

__global__ void __launch_bounds__(BLOCK, 3) lstm_fused_kernel(
    const float* __restrict__ x,
    const float* __restrict__ Wih0, const float* __restrict__ Whh0,
    const float* __restrict__ bih0, const float* __restrict__ bhh0,
    const float* __restrict__ Wih1, const float* __restrict__ Whh1,
    const float* __restrict__ bih1, const float* __restrict__ bhh1,
    const float* __restrict__ Wout, const float* __restrict__ bout,
    float* __restrict__ out)
{
    extern __shared__ unsigned int smh[];
    u64* smw = ((u64*)smh) + WG1_U64;
    const int tid  = threadIdx.x;
    const int lane = tid & 31;
    const int r    = tid & 3;                     // unit index / output quarter

    // ---- stage Wout as fp16 half2 with per-r column permutation ----
    for (int idx = tid; idx < SMW16; idx += BLOCK) {
        int c  = idx >> 4;
        int r4 = (idx >> 2) & 3;
        int q  = idx & 3;
        int srcc = (c & ~3) | ((c & 3) ^ r4);
        int row0 = 7 * r4 + 2 * q;                // q=3 hi is dummy
        float lo = Wout[row0 * 800 + srcc];
        float hi = (q < 3) ? Wout[(row0 + 1) * 800 + srcc] : 0.0f;
        __half2 h2v = __floats2half2_rn(lo, hi);
        smh[idx] = *(unsigned int*)&h2v;
    }
    // ---- stage layer-2 gate weights (0.5-prescaled), u64[4r][2][8] ----
    if (tid < 64) {
        int rr = tid >> 4, k = tid & 15;
        int which = k >> 3, in = k & 7;
        int cs = rr ^ (in & 3);                    // all L2 inputs permuted
        const float* src = (in < 4) ? Wih1 : Whh1;
        u64 v;
        if (which == 0)        // IF lanes: both sigmoid -> x0.5
            v = pack2(0.5f * src[(0 + rr) * 4 + cs], 0.5f * src[(4 + rr) * 4 + cs]);
        else                   // GO lanes: g tanh x1, o sigmoid x0.5
            v = pack2(       src[(8 + rr) * 4 + cs], 0.5f * src[(12 + rr) * 4 + cs]);
        smw[rr * 16 + which * 8 + in] = v;
    }
    __syncthreads();

    // ---- layer-1 gate weights -> registers (32 regs) ----
    u64 wIF0[8], wGO0[8];
    #pragma unroll
    for (int in = 0; in < 4; in++) {
        int cs = r ^ in;                           // h slots permuted; x not
        wIF0[in]     = pack2(0.5f * Wih0[(0  + r) * 4 + in], 0.5f * Wih0[(4  + r) * 4 + in]);
        wGO0[in]     = pack2(       Wih0[(8  + r) * 4 + in], 0.5f * Wih0[(12 + r) * 4 + in]);
        wIF0[4 + in] = pack2(0.5f * Whh0[(0  + r) * 4 + cs], 0.5f * Whh0[(4  + r) * 4 + cs]);
        wGO0[4 + in] = pack2(       Whh0[(8  + r) * 4 + cs], 0.5f * Whh0[(12 + r) * 4 + cs]);
    }
    const u64 bIF0 = pack2(0.5f * (bih0[r] + bhh0[r]),
                           0.5f * (bih0[4 + r] + bhh0[4 + r]));
    const u64 bGO0 = pack2(        bih0[8 + r] + bhh0[8 + r],
                           0.5f * (bih0[12 + r] + bhh0[12 + r]));
    const u64 bIF1 = pack2(0.5f * (bih1[r] + bhh1[r]),
                           0.5f * (bih1[4 + r] + bhh1[4 + r]));
    const u64 bGO1 = pack2(        bih1[8 + r] + bhh1[8 + r],
                           0.5f * (bih1[12 + r] + bhh1[12 + r]));

    const uint4* wop = (const uint4*)smh + r;
    const u64*   w1  = smw + r * 16;               // this thread's L2 weights

    // ---- persistent warp-level work stealing over 8-element sequences ----
    for (;;) {
        unsigned int g;
        if (lane == 0) g = atomicAdd(&g_ctr, 1u);
        g = __shfl_sync(0xffffffffu, g, 0);
        if (g >= NGROUPS) break;

        const int elem = (int)g * 8 + (lane >> 2);
        const float4* xp = (const float4*)(x + (size_t)elem * (TSEQ * 4));

        u64 h1P[4] = {0, 0, 0, 0};
        u64 h2P[4] = {0, 0, 0, 0};
        float c1 = 0.f, c2 = 0.f;
        u64 acc[4];
        acc[0] = pack2(bout[7 * r + 0], bout[7 * r + 1]);
        acc[1] = pack2(bout[7 * r + 2], bout[7 * r + 3]);
        acc[2] = pack2(bout[7 * r + 4], bout[7 * r + 5]);
        acc[3] = pack2(bout[7 * r + 6], 0.0f);

        #pragma unroll 1
        for (int tg = 0; tg < TSEQ; tg += 4) {
            if (tg + 8 < TSEQ) prefetchL2_(xp + tg + 8);

            #pragma unroll
            for (int u = 0; u < 4; u++) {
                const int t = tg + u;
                const float4 xt = xp[t];

                // ---- layer 1 (register weights) ----
                u64 xP[4];
                xP[0] = pack2(xt.x, xt.x); xP[1] = pack2(xt.y, xt.y);
                xP[2] = pack2(xt.z, xt.z); xP[3] = pack2(xt.w, xt.w);
                float h1 = unit_step(xP, h1P, wIF0, wGO0, bIF0, bGO0, c1);
                {
                    float a1 = __shfl_xor_sync(0xffffffffu, h1, 1);
                    float a2 = __shfl_xor_sync(0xffffffffu, h1, 2);
                    float a3 = __shfl_xor_sync(0xffffffffu, h1, 3);
                    h1P[0] = pack2(h1, h1); h1P[1] = pack2(a1, a1);
                    h1P[2] = pack2(a2, a2); h1P[3] = pack2(a3, a3);
                }

                // ---- layer 2 (smem weights, broadcast LDS) ----
                float h2 = unit_step(h1P, h2P, w1, w1 + 8, bIF1, bGO1, c2);
                {
                    float a1 = __shfl_xor_sync(0xffffffffu, h2, 1);
                    float a2 = __shfl_xor_sync(0xffffffffu, h2, 2);
                    float a3 = __shfl_xor_sync(0xffffffffu, h2, 3);
                    h2P[0] = pack2(h2, h2); h2P[1] = pack2(a1, a1);
                    h2P[2] = pack2(a2, a2); h2P[3] = pack2(a3, a3);
                }

                // ---- GEMV: fp16 weights, one LDS.128 per column ----
                #pragma unroll
                for (int s = 0; s < 4; s++) {
                    uint4 w = wop[(size_t)(4 * t + s) * 4];
                    float2 f0 = __half22float2(*(__half2*)&w.x);
                    float2 f1 = __half22float2(*(__half2*)&w.y);
                    float2 f2 = __half22float2(*(__half2*)&w.z);
                    float2 f3 = __half22float2(*(__half2*)&w.w);
                    acc[0] = fma2(h2P[s], pack2(f0.x, f0.y), acc[0]);
                    acc[1] = fma2(h2P[s], pack2(f1.x, f1.y), acc[1]);
                    acc[2] = fma2(h2P[s], pack2(f2.x, f2.y), acc[2]);
                    acc[3] = fma2(h2P[s], pack2(f3.x, f3.y), acc[3]);
                }
            }
        }

        // ---- write 7 outputs for this element ----
        float* op = out + (size_t)elem * 28 + 7 * r;
        float o0, o1, o2, o3, o4, o5, o6, dummy;
        unpack2(o0, o1, acc[0]); unpack2(o2, o3, acc[1]);
        unpack2(o4, o5, acc[2]); unpack2(o6, dummy, acc[3]);
        op[0] = o0; op[1] = o1; op[2] = o2; op[3] = o3;
        op[4] = o4; op[5] = o5; op[6] = o6;
    }
}

extern "C" void kernel_launch(void* const* d_in, const int* in_sizes, int n_in,
                              void* d_out, int out_size)
{
    const float* x    = (const float*)d_in[0];
    const float* Wih0 = (const float*)d_in[1];
    const float* Whh0 = (const float*)d_in[2];
    const float* bih0 = (const float*)d_in[3];
    const float* bhh0 = (const float*)d_in[4];
    const float* Wih1 = (const float*)d_in[5];
    const float* Whh1 = (const float*)d_in[6];
    const float* bih1 = (const float*)d_in[7];
    const float* bhh1 = (const float*)d_in[8];
    const float* Wout = (const float*)d_in[9];
    const float* bout = (const float*)d_in[10];
    float* out = (float*)d_out;

    int nsm = 148;
    cudaDeviceGetAttribute(&nsm, cudaDevAttrMultiProcessorCount, 0);
    const int grid = 3 * nsm;                     // 3 CTAs per SM

    cudaFuncSetAttribute(lstm_fused_kernel,
                         cudaFuncAttributeMaxDynamicSharedMemorySize, SM_BYTES);

    init_ctr_kernel<<<1, 1>>>();
    lstm_fused_kernel<<<grid, BLOCK, SM_BYTES>>>(
        x, Wih0, Whh0, bih0, bhh0, Wih1, Whh1, bih1, bhh1, Wout, bout, out);
}

// round 14
// speedup vs baseline: 1.5801x; 1.5801x over previous
#include <cuda_runtime.h>

#define BLOCK 256
#define TSEQ  200
#define NELEM 32768
#define NGROUPS (NELEM / 16)    // 16 elements per warp-sequence (2 per thread)

typedef unsigned long long u64;

__device__ unsigned int g_ctr;

__global__ void init_ctr_kernel() { g_ctr = 0u; }

// ---- tanh.approx-based activations (MUFU.TANH: ~1.4e-5 abs err) ----
__device__ __forceinline__ float tanha_(float x) {
    float y; asm("tanh.approx.f32 %0, %1;" : "=f"(y) : "f"(x)); return y;
}

// ---- packed f32x2 ops ----
__device__ __forceinline__ u64 fma2(u64 a, u64 b, u64 c) {
    u64 d; asm("fma.rn.f32x2 %0, %1, %2, %3;" : "=l"(d) : "l"(a), "l"(b), "l"(c));
    return d;
}
__device__ __forceinline__ u64 pack2(float lo, float hi) {
    u64 r; asm("mov.b64 %0, {%1, %2};" : "=l"(r) : "f"(lo), "f"(hi)); return r;
}
__device__ __forceinline__ void unpack2(float& lo, float& hi, u64 v) {
    asm("mov.b64 {%0, %1}, %2;" : "=f"(lo), "=f"(hi) : "l"(v));
}

// smem: Wout packs. [800 phys-col][4 r][4 qpack] u64 = 12800 u64 = 100 KB.
// phys col (4t+s) for r-class r holds logical column 4t + (s^r) (slot s = unit r^s).
#define SM_U64 12800

// one LSTM unit step. gIF lanes=(i,f), gGO lanes=(g,o).
// i/f/o rows and biases PRE-SCALED by 0.5 -> sigmoid = fma(tanh,.5,.5).
__device__ __forceinline__ float unit_step(
    const u64* __restrict__ inA, const u64* __restrict__ inB,
    const u64* __restrict__ wIF, const u64* __restrict__ wGO,
    u64 bIF, u64 bGO, float& c)
{
    u64 gIF = bIF, gGO = bGO;
    #pragma unroll
    for (int in = 0; in < 4; in++) {
        gIF = fma2(inA[in], wIF[in], gIF);
        gGO = fma2(inA[in], wGO[in], gGO);
    }
    #pragma unroll
    for (int in = 0; in < 4; in++) {
        gIF = fma2(inB[in], wIF[4 + in], gIF);
        gGO = fma2(inB[in], wGO[4 + in], gGO);
    }
    float iv, fv, gv, ov;
    unpack2(iv, fv, gIF);
    unpack2(gv, ov, gGO);
    float ti = tanha_(iv), tf = tanha_(fv), tg = tanha_(gv), to = tanha_(ov);
    float si = fmaf(ti, 0.5f, 0.5f);
    float sf = fmaf(tf, 0.5f, 0.5f);
    float so = fmaf(to, 0.5f, 0.5f);
    c = fmaf(sf, c, si * tg);
    return so * tanha_(c);
}

// butterfly + rebuild dup packs (3 independent shuffles)
__device__ __forceinline__ void bfly_packs(float h, u64* P) {
    float a1 = __shfl_xor_sync(0xffffffffu, h, 1);
    float a2 = __shfl_xor_sync(0xffffffffu, h, 2);
    float a3 = __shfl_xor_sync(0xffffffffu, h, 3);
    P[0] = pack2(h, h); P[1] = pack2(a1, a1);
    P[2] = pack2(a2, a2); P[3] = pack2(a3, a3);
}

__global__ void __launch_bounds__(BLOCK, 1) lstm_fused_kernel(
    const float* __restrict__ x,
    const float* __restrict__ Wih0, const float* __restrict__ Whh0,
    const float* __restrict__ bih0, const float* __restrict__ bhh0,
    const float* __restrict__ Wih1, const float* __restrict__ Whh1,
    const float* __restrict__ bih1, const float* __restrict__ bhh1,
    const float* __restrict__ Wout, const float* __restrict__ bout,
    float* __restrict__ out)
{
    extern __shared__ u64 smu[];
    const int tid  = threadIdx.x;
    const int lane = tid & 31;
    const int r    = tid & 3;                     // unit index / output quarter

    // ---- stage Wout packs with per-r column permutation (once per CTA) ----
    for (int idx = tid; idx < SM_U64; idx += BLOCK) {
        int c  = idx >> 4;
        int r4 = (idx >> 2) & 3;
        int q  = idx & 3;
        int srcc = (c & ~3) | ((c & 3) ^ r4);
        int row0 = 7 * r4 + 2 * q;                // q=3 hi is dummy
        float lo = Wout[row0 * 800 + srcc];
        float hi = (q < 3) ? Wout[(row0 + 1) * 800 + srcc] : 0.0f;
        smu[idx] = pack2(lo, hi);
    }
    __syncthreads();

    // ---- gate weights -> registers, 0.5-prescaled for sigmoid gates ----
    u64 wIF0[8], wGO0[8], wIF1[8], wGO1[8];
    #pragma unroll
    for (int in = 0; in < 4; in++) {
        int cs = r ^ in;                           // permuted column for h slots
        wIF0[in]     = pack2(0.5f * Wih0[(0  + r) * 4 + in], 0.5f * Wih0[(4  + r) * 4 + in]);
        wGO0[in]     = pack2(       Wih0[(8  + r) * 4 + in], 0.5f * Wih0[(12 + r) * 4 + in]);
        wIF0[4 + in] = pack2(0.5f * Whh0[(0  + r) * 4 + cs], 0.5f * Whh0[(4  + r) * 4 + cs]);
        wGO0[4 + in] = pack2(       Whh0[(8  + r) * 4 + cs], 0.5f * Whh0[(12 + r) * 4 + cs]);
        wIF1[in]     = pack2(0.5f * Wih1[(0  + r) * 4 + cs], 0.5f * Wih1[(4  + r) * 4 + cs]);
        wGO1[in]     = pack2(       Wih1[(8  + r) * 4 + cs], 0.5f * Wih1[(12 + r) * 4 + cs]);
        wIF1[4 + in] = pack2(0.5f * Whh1[(0  + r) * 4 + cs], 0.5f * Whh1[(4  + r) * 4 + cs]);
        wGO1[4 + in] = pack2(       Whh1[(8  + r) * 4 + cs], 0.5f * Whh1[(12 + r) * 4 + cs]);
    }
    const u64 bIF0 = pack2(0.5f * (bih0[r] + bhh0[r]),
                           0.5f * (bih0[4 + r] + bhh0[4 + r]));
    const u64 bGO0 = pack2(        bih0[8 + r] + bhh0[8 + r],
                           0.5f * (bih0[12 + r] + bhh0[12 + r]));
    const u64 bIF1 = pack2(0.5f * (bih1[r] + bhh1[r]),
                           0.5f * (bih1[4 + r] + bhh1[4 + r]));
    const u64 bGO1 = pack2(        bih1[8 + r] + bhh1[8 + r],
                           0.5f * (bih1[12 + r] + bhh1[12 + r]));

    const u64 accInit0 = pack2(bout[7 * r + 0], bout[7 * r + 1]);
    const u64 accInit1 = pack2(bout[7 * r + 2], bout[7 * r + 3]);
    const u64 accInit2 = pack2(bout[7 * r + 4], bout[7 * r + 5]);
    const u64 accInit3 = pack2(bout[7 * r + 6], 0.0f);

    const ulonglong2* wop = (const ulonglong2*)smu + (size_t)r * 2;

    // ---- persistent warp-level work stealing over 16-element sequences ----
    for (;;) {
        unsigned int g;
        if (lane == 0) g = atomicAdd(&g_ctr, 1u);
        g = __shfl_sync(0xffffffffu, g, 0);
        if (g >= NGROUPS) break;

        const int elemA = (int)g * 16 + (lane >> 2);   // quad's element A
        const int elemB = elemA + 8;                   // quad's element B
        const float4* xpA = (const float4*)(x + (size_t)elemA * (TSEQ * 4));
        const float4* xpB = (const float4*)(x + (size_t)elemB * (TSEQ * 4));

        u64 h1PA[4] = {0,0,0,0}, h2PA[4] = {0,0,0,0};
        u64 h1PB[4] = {0,0,0,0}, h2PB[4] = {0,0,0,0};
        float c1A = 0.f, c2A = 0.f, c1B = 0.f, c2B = 0.f;
        u64 accA[4] = {accInit0, accInit1, accInit2, accInit3};
        u64 accB[4] = {accInit0, accInit1, accInit2, accInit3};

        #pragma unroll 1
        for (int tg = 0; tg < TSEQ; tg += 2) {
            // 4 independent x loads (MLP=4)
            float4 xA0 = xpA[tg], xA1 = xpA[tg + 1];
            float4 xB0 = xpB[tg], xB1 = xpB[tg + 1];

            #pragma unroll
            for (int u = 0; u < 2; u++) {
                const int t = tg + u;
                const float4 xtA = u ? xA1 : xA0;
                const float4 xtB = u ? xB1 : xB0;

                // ---- layer 1: two independent chains ----
                u64 xPA[4], xPB[4];
                xPA[0] = pack2(xtA.x, xtA.x); xPA[1] = pack2(xtA.y, xtA.y);
                xPA[2] = pack2(xtA.z, xtA.z); xPA[3] = pack2(xtA.w, xtA.w);
                xPB[0] = pack2(xtB.x, xtB.x); xPB[1] = pack2(xtB.y, xtB.y);
                xPB[2] = pack2(xtB.z, xtB.z); xPB[3] = pack2(xtB.w, xtB.w);
                float h1A = unit_step(xPA, h1PA, wIF0, wGO0, bIF0, bGO0, c1A);
                float h1B = unit_step(xPB, h1PB, wIF0, wGO0, bIF0, bGO0, c1B);
                bfly_packs(h1A, h1PA);
                bfly_packs(h1B, h1PB);

                // ---- layer 2: two independent chains ----
                float h2A = unit_step(h1PA, h2PA, wIF1, wGO1, bIF1, bGO1, c2A);
                float h2B = unit_step(h1PB, h2PB, wIF1, wGO1, bIF1, bGO1, c2B);
                bfly_packs(h2A, h2PA);
                bfly_packs(h2B, h2PB);

                // ---- GEMV: ONE weight load serves BOTH elements ----
                #pragma unroll
                for (int s = 0; s < 4; s++) {
                    const ulonglong2* wrow = wop + (size_t)(4 * t + s) * 8;
                    ulonglong2 w0 = wrow[0];
                    ulonglong2 w1 = wrow[1];
                    accA[0] = fma2(h2PA[s], w0.x, accA[0]);
                    accA[1] = fma2(h2PA[s], w0.y, accA[1]);
                    accA[2] = fma2(h2PA[s], w1.x, accA[2]);
                    accA[3] = fma2(h2PA[s], w1.y, accA[3]);
                    accB[0] = fma2(h2PB[s], w0.x, accB[0]);
                    accB[1] = fma2(h2PB[s], w0.y, accB[1]);
                    accB[2] = fma2(h2PB[s], w1.x, accB[2]);
                    accB[3] = fma2(h2PB[s], w1.y, accB[3]);
                }
            }
        }

        // ---- write 7 outputs per element ----
        {
            float* op = out + (size_t)elemA * 28 + 7 * r;
            float o0, o1, o2, o3, o4, o5, o6, dm;
            unpack2(o0, o1, accA[0]); unpack2(o2, o3, accA[1]);
            unpack2(o4, o5, accA[2]); unpack2(o6, dm, accA[3]);
            op[0] = o0; op[1] = o1; op[2] = o2; op[3] = o3;
            op[4] = o4; op[5] = o5; op[6] = o6;
        }
        {
            float* op = out + (size_t)elemB * 28 + 7 * r;
            float o0, o1, o2, o3, o4, o5, o6, dm;
            unpack2(o0, o1, accB[0]); unpack2(o2, o3, accB[1]);
            unpack2(o4, o5, accB[2]); unpack2(o6, dm, accB[3]);
            op[0] = o0; op[1] = o1; op[2] = o2; op[3] = o3;
            op[4] = o4; op[5] = o5; op[6] = o6;
        }
    }
}

extern "C" void kernel_launch(void* const* d_in, const int* in_sizes, int n_in,
                              void* d_out, int out_size)
{
    const float* x    = (const float*)d_in[0];
    const float* Wih0 = (const float*)d_in[1];
    const float* Whh0 = (const float*)d_in[2];
    const float* bih0 = (const float*)d_in[3];
    const float* bhh0 = (const float*)d_in[4];
    const float* Wih1 = (const float*)d_in[5];
    const float* Whh1 = (const float*)d_in[6];
    const float* bih1 = (const float*)d_in[7];
    const float* bhh1 = (const float*)d_in[8];
    const float* Wout = (const float*)d_in[9];
    const float* bout = (const float*)d_in[10];
    float* out = (float*)d_out;

    const int smem_bytes = SM_U64 * sizeof(u64);     // 102400 B

    int nsm = 148;
    cudaDeviceGetAttribute(&nsm, cudaDevAttrMultiProcessorCount, 0);
    const int grid = nsm;                            // 1 persistent CTA per SM

    cudaFuncSetAttribute(lstm_fused_kernel,
                         cudaFuncAttributeMaxDynamicSharedMemorySize, smem_bytes);

    init_ctr_kernel<<<1, 1>>>();
    lstm_fused_kernel<<<grid, BLOCK, smem_bytes>>>(
        x, Wih0, Whh0, bih0, bhh0, Wih1, Whh1, bih1, bhh1, Wout, bout, out);
}

// round 15
// speedup vs baseline: 1.7555x; 1.1110x over previous
#include <cuda_runtime.h>

#define BLOCK 256
#define TSEQ  200
#define NELEM 32768
#define NGROUPS (NELEM / 8)     // 8 elements per warp-sequence

typedef unsigned long long u64;

__device__ unsigned int g_ctr;

__global__ void init_ctr_kernel() { g_ctr = 0u; }

// ---- tanh.approx-based activations (MUFU.TANH: ~1.4e-5 abs err) ----
__device__ __forceinline__ float tanha_(float x) {
    float y; asm("tanh.approx.f32 %0, %1;" : "=f"(y) : "f"(x)); return y;
}

// ---- packed f32x2 ops ----
__device__ __forceinline__ u64 fma2(u64 a, u64 b, u64 c) {
    u64 d; asm("fma.rn.f32x2 %0, %1, %2, %3;" : "=l"(d) : "l"(a), "l"(b), "l"(c));
    return d;
}
__device__ __forceinline__ u64 pack2(float lo, float hi) {
    u64 r; asm("mov.b64 %0, {%1, %2};" : "=l"(r) : "f"(lo), "f"(hi)); return r;
}
__device__ __forceinline__ void unpack2(float& lo, float& hi, u64 v) {
    asm("mov.b64 {%0, %1}, %2;" : "=f"(lo), "=f"(hi) : "l"(v));
}
__device__ __forceinline__ void prefetchL2_(const void* p) {
    asm volatile("prefetch.global.L2 [%0];" :: "l"(p));
}

// smem: Wout packs. [800 phys-col][4 r][4 qpack] u64 = 12800 u64 = 100 KB.
// phys col (4t+s) for r-class r holds logical column 4t + (s^r) (slot s = unit r^s).
#define SM_U64 12800

// one LSTM unit step. gIF lanes=(i,f), gGO lanes=(g,o).
// i/f/o rows and biases PRE-SCALED by 0.5 -> sigmoid = fma(tanh,.5,.5).
__device__ __forceinline__ float unit_step(
    const u64* __restrict__ inA, const u64* __restrict__ inB,
    const u64* __restrict__ wIF, const u64* __restrict__ wGO,
    u64 bIF, u64 bGO, float& c)
{
    u64 gIF = bIF, gGO = bGO;
    #pragma unroll
    for (int in = 0; in < 4; in++) {
        gIF = fma2(inA[in], wIF[in], gIF);
        gGO = fma2(inA[in], wGO[in], gGO);
    }
    #pragma unroll
    for (int in = 0; in < 4; in++) {
        gIF = fma2(inB[in], wIF[4 + in], gIF);
        gGO = fma2(inB[in], wGO[4 + in], gGO);
    }
    float iv, fv, gv, ov;
    unpack2(iv, fv, gIF);
    unpack2(gv, ov, gGO);
    float ti = tanha_(iv), tf = tanha_(fv), tg = tanha_(gv), to = tanha_(ov);
    float si = fmaf(ti, 0.5f, 0.5f);
    float sf = fmaf(tf, 0.5f, 0.5f);
    float so = fmaf(to, 0.5f, 0.5f);
    c = fmaf(sf, c, si * tg);
    return so * tanha_(c);
}

__global__ void __launch_bounds__(BLOCK, 2) lstm_fused_kernel(
    const float* __restrict__ x,
    const float* __restrict__ Wih0, const float* __restrict__ Whh0,
    const float* __restrict__ bih0, const float* __restrict__ bhh0,
    const float* __restrict__ Wih1, const float* __restrict__ Whh1,
    const float* __restrict__ bih1, const float* __restrict__ bhh1,
    const float* __restrict__ Wout, const float* __restrict__ bout,
    float* __restrict__ out)
{
    extern __shared__ u64 smu[];
    const int tid  = threadIdx.x;
    const int lane = tid & 31;
    const int r    = tid & 3;                     // unit index / output quarter

    // ---- stage Wout packs with per-r column permutation (once per CTA) ----
    for (int idx = tid; idx < SM_U64; idx += BLOCK) {
        int c  = idx >> 4;
        int r4 = (idx >> 2) & 3;
        int q  = idx & 3;
        int srcc = (c & ~3) | ((c & 3) ^ r4);     // logical column for this r-class
        int row0 = 7 * r4 + 2 * q;                // rows 7r .. 7r+6 (q=3 hi is dummy)
        float lo = Wout[row0 * 800 + srcc];
        float hi = (q < 3) ? Wout[(row0 + 1) * 800 + srcc] : 0.0f;
        smu[idx] = pack2(lo, hi);
    }
    __syncthreads();

    // ---- gate weights -> registers, 0.5-prescaled for sigmoid gates ----
    u64 wIF0[8], wGO0[8], wIF1[8], wGO1[8];
    #pragma unroll
    for (int in = 0; in < 4; in++) {
        int cs = r ^ in;                           // permuted column for h slots
        wIF0[in]     = pack2(0.5f * Wih0[(0  + r) * 4 + in], 0.5f * Wih0[(4  + r) * 4 + in]);
        wGO0[in]     = pack2(       Wih0[(8  + r) * 4 + in], 0.5f * Wih0[(12 + r) * 4 + in]);
        wIF0[4 + in] = pack2(0.5f * Whh0[(0  + r) * 4 + cs], 0.5f * Whh0[(4  + r) * 4 + cs]);
        wGO0[4 + in] = pack2(       Whh0[(8  + r) * 4 + cs], 0.5f * Whh0[(12 + r) * 4 + cs]);
        wIF1[in]     = pack2(0.5f * Wih1[(0  + r) * 4 + cs], 0.5f * Wih1[(4  + r) * 4 + cs]);
        wGO1[in]     = pack2(       Wih1[(8  + r) * 4 + cs], 0.5f * Wih1[(12 + r) * 4 + cs]);
        wIF1[4 + in] = pack2(0.5f * Whh1[(0  + r) * 4 + cs], 0.5f * Whh1[(4  + r) * 4 + cs]);
        wGO1[4 + in] = pack2(       Whh1[(8  + r) * 4 + cs], 0.5f * Whh1[(12 + r) * 4 + cs]);
    }
    const u64 bIF0 = pack2(0.5f * (bih0[r] + bhh0[r]),
                           0.5f * (bih0[4 + r] + bhh0[4 + r]));
    const u64 bGO0 = pack2(        bih0[8 + r] + bhh0[8 + r],
                           0.5f * (bih0[12 + r] + bhh0[12 + r]));
    const u64 bIF1 = pack2(0.5f * (bih1[r] + bhh1[r]),
                           0.5f * (bih1[4 + r] + bhh1[4 + r]));
    const u64 bGO1 = pack2(        bih1[8 + r] + bhh1[8 + r],
                           0.5f * (bih1[12 + r] + bhh1[12 + r]));

    const u64 accInit0 = pack2(bout[7 * r + 0], bout[7 * r + 1]);
    const u64 accInit1 = pack2(bout[7 * r + 2], bout[7 * r + 3]);
    const u64 accInit2 = pack2(bout[7 * r + 4], bout[7 * r + 5]);
    const u64 accInit3 = pack2(bout[7 * r + 6], 0.0f);

    const ulonglong2* wop = (const ulonglong2*)smu + (size_t)r * 2;

    // ---- persistent warp-level work stealing over 8-element sequences ----
    for (;;) {
        unsigned int g;
        if (lane == 0) g = atomicAdd(&g_ctr, 1u);
        g = __shfl_sync(0xffffffffu, g, 0);
        if (g >= NGROUPS) break;

        const int elem = (int)g * 8 + (lane >> 2);
        const float4* xp = (const float4*)(x + (size_t)elem * (TSEQ * 4));

        u64 h1P[4] = {0, 0, 0, 0};                // pack2(h1s[s], h1s[s])
        u64 h2P[4] = {0, 0, 0, 0};
        float c1 = 0.f, c2 = 0.f;
        u64 acc[4] = {accInit0, accInit1, accInit2, accInit3};

        // 8-step unrolled body: wide scheduling window, x loaded inline
        // (zero extra live state; x latency proven covered)
        #pragma unroll 1
        for (int tg = 0; tg < TSEQ; tg += 8) {
            if (tg + 8 < TSEQ) prefetchL2_(xp + tg + 8);

            #pragma unroll
            for (int u = 0; u < 8; u++) {
                const int t = tg + u;
                const float4 xt = xp[t];          // inline load, no live buffer

                // ---- layer 1 ----
                u64 xP[4];
                xP[0] = pack2(xt.x, xt.x); xP[1] = pack2(xt.y, xt.y);
                xP[2] = pack2(xt.z, xt.z); xP[3] = pack2(xt.w, xt.w);
                float h1 = unit_step(xP, h1P, wIF0, wGO0, bIF0, bGO0, c1);
                {
                    float a1 = __shfl_xor_sync(0xffffffffu, h1, 1);
                    float a2 = __shfl_xor_sync(0xffffffffu, h1, 2);
                    float a3 = __shfl_xor_sync(0xffffffffu, h1, 3);
                    h1P[0] = pack2(h1, h1); h1P[1] = pack2(a1, a1);
                    h1P[2] = pack2(a2, a2); h1P[3] = pack2(a3, a3);
                }

                // ---- layer 2 ----
                float h2 = unit_step(h1P, h2P, wIF1, wGO1, bIF1, bGO1, c2);
                {
                    float a1 = __shfl_xor_sync(0xffffffffu, h2, 1);
                    float a2 = __shfl_xor_sync(0xffffffffu, h2, 2);
                    float a3 = __shfl_xor_sync(0xffffffffu, h2, 3);
                    h2P[0] = pack2(h2, h2); h2P[1] = pack2(a1, a1);
                    h2P[2] = pack2(a2, a2); h2P[3] = pack2(a3, a3);
                }

                // ---- GEMV: reuses h2P; sinks into next steps' shadows ----
                #pragma unroll
                for (int s = 0; s < 4; s++) {
                    const ulonglong2* wrow = wop + (size_t)(4 * t + s) * 8;
                    ulonglong2 w0 = wrow[0];
                    ulonglong2 w1 = wrow[1];
                    acc[0] = fma2(h2P[s], w0.x, acc[0]);
                    acc[1] = fma2(h2P[s], w0.y, acc[1]);
                    acc[2] = fma2(h2P[s], w1.x, acc[2]);
                    acc[3] = fma2(h2P[s], w1.y, acc[3]);
                }
            }
        }

        // ---- write 7 outputs for this element ----
        float* op = out + (size_t)elem * 28 + 7 * r;
        float o0, o1, o2, o3, o4, o5, o6, dummy;
        unpack2(o0, o1, acc[0]); unpack2(o2, o3, acc[1]);
        unpack2(o4, o5, acc[2]); unpack2(o6, dummy, acc[3]);
        op[0] = o0; op[1] = o1; op[2] = o2; op[3] = o3;
        op[4] = o4; op[5] = o5; op[6] = o6;
    }
}

extern "C" void kernel_launch(void* const* d_in, const int* in_sizes, int n_in,
                              void* d_out, int out_size)
{
    const float* x    = (const float*)d_in[0];
    const float* Wih0 = (const float*)d_in[1];
    const float* Whh0 = (const float*)d_in[2];
    const float* bih0 = (const float*)d_in[3];
    const float* bhh0 = (const float*)d_in[4];
    const float* Wih1 = (const float*)d_in[5];
    const float* Whh1 = (const float*)d_in[6];
    const float* bih1 = (const float*)d_in[7];
    const float* bhh1 = (const float*)d_in[8];
    const float* Wout = (const float*)d_in[9];
    const float* bout = (const float*)d_in[10];
    float* out = (float*)d_out;

    const int smem_bytes = SM_U64 * sizeof(u64);     // 102400 B

    int nsm = 148;
    cudaDeviceGetAttribute(&nsm, cudaDevAttrMultiProcessorCount, 0);
    const int grid = 2 * nsm;

    cudaFuncSetAttribute(lstm_fused_kernel,
                         cudaFuncAttributeMaxDynamicSharedMemorySize, smem_bytes);

    init_ctr_kernel<<<1, 1>>>();
    lstm_fused_kernel<<<grid, BLOCK, smem_bytes>>>(
        x, Wih0, Whh0, bih0, bhh0, Wih1, Whh1, bih1, bhh1, Wout, bout, out);
}